// round 5
// baseline (speedup 1.0000x reference)
#include <cuda_runtime.h>
#include <cstdint>
#include <cstddef>

#define BDIM 8192
#define CDIM 256
#define NITER 100
#define TILE 16
#define NT (BDIM / TILE)          // 512 tiles per row
#define MARGIN 25.0f
#define L2E 1.4426950408889634f
#define LN2 0.69314718055994531f

// Scratch: __device__ globals (no cudaMalloc allowed)
__device__ __align__(256) float g_M [(size_t)BDIM * BDIM];  // M[i][j]  = 2*x_i.y_j
__device__ __align__(256) float g_MT[(size_t)BDIM * BDIM];  // MT[j][i] = M[i][j]
__device__ __align__(256) float g_TR[(size_t)BDIM * NT];    // row tile-max of M
__device__ __align__(256) float g_TC[(size_t)BDIM * NT];    // row tile-max of MT
__device__ __align__(256) float g_a[BDIM];
__device__ __align__(256) float g_b[BDIM];

__device__ __forceinline__ float ex2f(float x) {
    float y; asm("ex2.approx.f32 %0, %1;" : "=f"(y) : "f"(x)); return y;
}
__device__ __forceinline__ float lg2f(float x) {
    float y; asm("lg2.approx.f32 %0, %1;" : "=f"(y) : "f"(x)); return y;
}

// ---------------------------------------------------------------------------
// b init: b[j] = -||y_j||^2   (one warp per row, 8 rows per block)
// ---------------------------------------------------------------------------
__global__ __launch_bounds__(256) void init_b_kernel(const float* __restrict__ Y)
{
    int warp = threadIdx.x >> 5, lane = threadIdx.x & 31;
    int row = (blockIdx.x << 3) + warp;
    const float4* yr = (const float4*)Y + (size_t)row * (CDIM / 4);
    float4 v0 = yr[lane];
    float4 v1 = yr[lane + 32];
    float ss = 0.f;
    ss = fmaf(v0.x, v0.x, ss); ss = fmaf(v0.y, v0.y, ss);
    ss = fmaf(v0.z, v0.z, ss); ss = fmaf(v0.w, v0.w, ss);
    ss = fmaf(v1.x, v1.x, ss); ss = fmaf(v1.y, v1.y, ss);
    ss = fmaf(v1.z, v1.z, ss); ss = fmaf(v1.w, v1.w, ss);
    #pragma unroll
    for (int off = 16; off; off >>= 1)
        ss += __shfl_xor_sync(0xffffffffu, ss, off);
    if (lane == 0) g_b[row] = -ss;
}

// ---------------------------------------------------------------------------
// GEMM: M = 2 * X * Y^T, plus transposed copy MT.
// ---------------------------------------------------------------------------
__global__ __launch_bounds__(256) void gemm_kernel(const float* __restrict__ X,
                                                   const float* __restrict__ Y)
{
    __shared__ float As[16][128];
    __shared__ float Bs[16][128];

    const int tid = threadIdx.x;
    const int tx = tid & 15;
    const int ty = tid >> 4;
    const int i0 = blockIdx.y << 7;
    const int j0 = blockIdx.x << 7;

    const float4* X4 = (const float4*)X;
    const float4* Y4 = (const float4*)Y;

    float acc[8][8];
    #pragma unroll
    for (int r = 0; r < 8; r++)
        #pragma unroll
        for (int c = 0; c < 8; c++) acc[r][c] = 0.f;

    for (int k0 = 0; k0 < CDIM; k0 += 16) {
        #pragma unroll
        for (int p = 0; p < 2; p++) {
            int f = tid + (p << 8);
            int r = f >> 2;
            int q = f & 3;
            float4 a = X4[(size_t)(i0 + r) * (CDIM / 4) + (k0 >> 2) + q];
            As[q * 4 + 0][r] = a.x; As[q * 4 + 1][r] = a.y;
            As[q * 4 + 2][r] = a.z; As[q * 4 + 3][r] = a.w;
            float4 b = Y4[(size_t)(j0 + r) * (CDIM / 4) + (k0 >> 2) + q];
            Bs[q * 4 + 0][r] = b.x; Bs[q * 4 + 1][r] = b.y;
            Bs[q * 4 + 2][r] = b.z; Bs[q * 4 + 3][r] = b.w;
        }
        __syncthreads();
        #pragma unroll
        for (int kk = 0; kk < 16; kk++) {
            float af[8], bf[8];
            *(float4*)&af[0] = *(const float4*)&As[kk][ty * 8];
            *(float4*)&af[4] = *(const float4*)&As[kk][ty * 8 + 4];
            *(float4*)&bf[0] = *(const float4*)&Bs[kk][tx * 8];
            *(float4*)&bf[4] = *(const float4*)&Bs[kk][tx * 8 + 4];
            #pragma unroll
            for (int r = 0; r < 8; r++)
                #pragma unroll
                for (int c = 0; c < 8; c++)
                    acc[r][c] = fmaf(af[r], bf[c], acc[r][c]);
        }
        __syncthreads();
    }

    #pragma unroll
    for (int r = 0; r < 8; r++) {
        int i = i0 + ty * 8 + r;
        float4 w0 = make_float4(2.f * acc[r][0], 2.f * acc[r][1],
                                2.f * acc[r][2], 2.f * acc[r][3]);
        float4 w1 = make_float4(2.f * acc[r][4], 2.f * acc[r][5],
                                2.f * acc[r][6], 2.f * acc[r][7]);
        float4* dst = (float4*)(g_M + (size_t)i * BDIM + j0 + tx * 8);
        dst[0] = w0; dst[1] = w1;
    }
    #pragma unroll
    for (int c = 0; c < 8; c++) {
        int j = j0 + tx * 8 + c;
        float4 t0 = make_float4(2.f * acc[0][c], 2.f * acc[1][c],
                                2.f * acc[2][c], 2.f * acc[3][c]);
        float4 t1 = make_float4(2.f * acc[4][c], 2.f * acc[5][c],
                                2.f * acc[6][c], 2.f * acc[7][c]);
        float4* dst = (float4*)(g_MT + (size_t)j * BDIM + i0 + ty * 8);
        dst[0] = t0; dst[1] = t1;
    }
}

// ---------------------------------------------------------------------------
// Tile max: TR[row][t] = max over 16 cols of M, TC likewise from MT.
// One warp per row; blocks 0..1023 -> M, 1024..2047 -> MT.
// ---------------------------------------------------------------------------
__global__ __launch_bounds__(256) void tilemax_kernel()
{
    const int half = blockIdx.x >> 10;
    const int row = ((blockIdx.x & 1023) << 3) + (threadIdx.x >> 5);
    const int lane = threadIdx.x & 31;
    const float4* src = (const float4*)((half ? g_MT : g_M) + (size_t)row * BDIM);
    float* dstrow = (half ? g_TC : g_TR) + (size_t)row * NT;

    #pragma unroll 4
    for (int k = 0; k < 64; k++) {
        float4 f = __ldcs(src + lane + 32 * k);
        float fm = fmaxf(fmaxf(f.x, f.y), fmaxf(f.z, f.w));
        fm = fmaxf(fm, __shfl_xor_sync(0xffffffffu, fm, 1));
        fm = fmaxf(fm, __shfl_xor_sync(0xffffffffu, fm, 2));
        if ((lane & 3) == 0) dstrow[(lane >> 2) + 8 * k] = fm;
    }
}

// ---------------------------------------------------------------------------
// Sparse LSE pass: dst[row] = -logsumexp_j( Mmat[row][j] + src[j] )
// Skips 16-col tiles whose upper bound T[row][t]+max(src tile) < m1 - MARGIN,
// where m1 is the true max of the best-bound tile (=> skipped terms < m*-25,
// total omitted mass < 1.2e-7 relative: below ex2.approx noise).
// ---------------------------------------------------------------------------
__global__ __launch_bounds__(256) void lse_sparse_kernel(const float* __restrict__ Mmat,
                                                         const float* __restrict__ Tmat,
                                                         const float* __restrict__ src,
                                                         float* __restrict__ dst)
{
    __shared__ float sb[BDIM];                 // src vector
    __shared__ float st[NT];                   // per-tile max of src
    __shared__ unsigned short slist[8][NT];    // per-warp selected tiles

    const int tid = threadIdx.x;
    const int lane = tid & 31, warp = tid >> 5;

    // stage src + compute per-16 tile max from registers
    float4* sb4 = (float4*)sb;
    const float4* s4 = (const float4*)src;
    #pragma unroll
    for (int k = 0; k < 8; k++) {
        float4 f = s4[tid + 256 * k];
        sb4[tid + 256 * k] = f;
        float fm = fmaxf(fmaxf(f.x, f.y), fmaxf(f.z, f.w));
        fm = fmaxf(fm, __shfl_xor_sync(0xffffffffu, fm, 1));
        fm = fmaxf(fm, __shfl_xor_sync(0xffffffffu, fm, 2));
        if ((tid & 3) == 0) st[(tid >> 2) + 64 * k] = fm;
    }
    __syncthreads();

    const int row = (blockIdx.x << 3) + warp;
    const float* Mrow = Mmat + (size_t)row * BDIM;

    // upper bounds per tile + warp argmax
    const float4* T4 = (const float4*)(Tmat + (size_t)row * NT);
    float ubv[16];
    float best = -3.0e38f; int bt = 0;
    #pragma unroll
    for (int u = 0; u < 4; u++) {
        float4 t = T4[lane + 32 * u];
        int tb = 4 * (lane + 32 * u);
        ubv[4*u+0] = t.x + st[tb+0]; ubv[4*u+1] = t.y + st[tb+1];
        ubv[4*u+2] = t.z + st[tb+2]; ubv[4*u+3] = t.w + st[tb+3];
        #pragma unroll
        for (int c = 0; c < 4; c++)
            if (ubv[4*u+c] > best) { best = ubv[4*u+c]; bt = tb + c; }
    }
    #pragma unroll
    for (int off = 16; off; off >>= 1) {
        float ov = __shfl_xor_sync(0xffffffffu, best, off);
        int   oi = __shfl_xor_sync(0xffffffffu, bt, off);
        if (ov > best || (ov == best && oi < bt)) { best = ov; bt = oi; }
    }
    const int ctstar = bt;

    // true max m1 of the best tile (lanes 0..15 hold its 16 elements)
    float vstar = -3.0e38f;
    if (lane < 16) vstar = __ldg(Mrow + ctstar * 16 + lane) + sb[ctstar * 16 + lane];
    float m1 = vstar;
    #pragma unroll
    for (int off = 16; off; off >>= 1)
        m1 = fmaxf(m1, __shfl_xor_sync(0xffffffffu, m1, off));

    float m = m1;
    float s = (lane < 16) ? ex2f((vstar - m1) * L2E) : 0.f;
    const float theta = m1 - MARGIN;

    // select tiles (exclude ctstar), compact into per-warp list
    int cnt = 0;
    #pragma unroll
    for (int u = 0; u < 4; u++)
        #pragma unroll
        for (int c = 0; c < 4; c++) {
            int t = 4 * (lane + 32 * u) + c;
            cnt += (ubv[4*u+c] >= theta && t != ctstar) ? 1 : 0;
        }
    int inc = cnt;
    #pragma unroll
    for (int d = 1; d < 32; d <<= 1) {
        int o = __shfl_up_sync(0xffffffffu, inc, d);
        if (lane >= d) inc += o;
    }
    int woff = inc - cnt;
    const int total = __shfl_sync(0xffffffffu, inc, 31);
    unsigned short* lst = slist[warp];
    #pragma unroll
    for (int u = 0; u < 4; u++)
        #pragma unroll
        for (int c = 0; c < 4; c++) {
            int t = 4 * (lane + 32 * u) + c;
            if (ubv[4*u+c] >= theta && t != ctstar)
                lst[woff++] = (unsigned short)t;
        }
    __syncwarp();

    // process selected tiles: lanes 0-15 -> tile idx p+2q, lanes 16-31 -> p+2q+1
    const int half16 = lane >> 4, off16 = lane & 15;
    for (int p = 0; p < total; p += 8) {
        float v[4];
        #pragma unroll
        for (int q = 0; q < 4; q++) {
            int idx = p + 2 * q + half16;
            if (idx < total) {
                int t = lst[idx];
                v[q] = __ldcs(Mrow + t * 16 + off16) + sb[t * 16 + off16];
            } else v[q] = -3.0e38f;
        }
        float lmax = fmaxf(fmaxf(v[0], v[1]), fmaxf(v[2], v[3]));
        float nm = fmaxf(m, lmax);
        s *= ex2f((m - nm) * L2E);
        m = nm;
        float mk = m * L2E;
        s += ex2f(fmaf(v[0], L2E, -mk));
        s += ex2f(fmaf(v[1], L2E, -mk));
        s += ex2f(fmaf(v[2], L2E, -mk));
        s += ex2f(fmaf(v[3], L2E, -mk));
    }

    // warp combine
    #pragma unroll
    for (int off = 16; off; off >>= 1) {
        float om = __shfl_xor_sync(0xffffffffu, m, off);
        float os = __shfl_xor_sync(0xffffffffu, s, off);
        float nm = fmaxf(m, om);
        s = s * ex2f((m - nm) * L2E) + os * ex2f((om - nm) * L2E);
        m = nm;
    }
    if (lane == 0) dst[row] = -(m + lg2f(s) * LN2);
}

// ---------------------------------------------------------------------------
// Final: out[i][:] = y[ argmax_j (M[i][j] + b[j]) ][:]   (full scan, runs once)
// ---------------------------------------------------------------------------
__global__ __launch_bounds__(256) void argmax_gather_kernel(const float* __restrict__ Y,
                                                            float* __restrict__ out)
{
    __shared__ float sb[BDIM];
    __shared__ float sval[8];
    __shared__ int   sidx[8];
    __shared__ int   sjbest;
    const int tid = threadIdx.x;
    const int lane = tid & 31, warp = tid >> 5;

    float4* sb4 = (float4*)sb;
    const float4* s4 = (const float4*)g_b;
    #pragma unroll
    for (int k = 0; k < 8; k++) sb4[tid + 256 * k] = s4[tid + 256 * k];
    __syncthreads();

    const int row0 = blockIdx.x << 3;
    for (int rr = 0; rr < 8; rr++) {
        const int row = row0 + rr;
        const float4* m4 = (const float4*)(g_M + (size_t)row * BDIM);

        float best = -3.0e38f;
        int bidx = 0x7fffffff;
        #pragma unroll
        for (int k = 0; k < 8; k++) {
            int f = tid + 256 * k;
            float4 m = __ldcs(m4 + f);
            float4 bb = sb4[f];
            float vx = m.x + bb.x, vy = m.y + bb.y, vz = m.z + bb.z, vw = m.w + bb.w;
            int j = f * 4;
            if (vx > best || (vx == best && j     < bidx)) { best = vx; bidx = j; }
            if (vy > best || (vy == best && j + 1 < bidx)) { best = vy; bidx = j + 1; }
            if (vz > best || (vz == best && j + 2 < bidx)) { best = vz; bidx = j + 2; }
            if (vw > best || (vw == best && j + 3 < bidx)) { best = vw; bidx = j + 3; }
        }
        #pragma unroll
        for (int off = 16; off; off >>= 1) {
            float ov = __shfl_xor_sync(0xffffffffu, best, off);
            int   oi = __shfl_xor_sync(0xffffffffu, bidx, off);
            if (ov > best || (ov == best && oi < bidx)) { best = ov; bidx = oi; }
        }
        if (lane == 0) { sval[warp] = best; sidx[warp] = bidx; }
        __syncthreads();
        if (tid == 0) {
            float bv = sval[0]; int bj = sidx[0];
            #pragma unroll
            for (int w = 1; w < 8; w++) {
                if (sval[w] > bv || (sval[w] == bv && sidx[w] < bj)) {
                    bv = sval[w]; bj = sidx[w];
                }
            }
            sjbest = bj;
        }
        __syncthreads();
        out[(size_t)row * CDIM + tid] = Y[(size_t)sjbest * CDIM + tid];
        __syncthreads();
    }
}

// ---------------------------------------------------------------------------
extern "C" void kernel_launch(void* const* d_in, const int* in_sizes, int n_in,
                              void* d_out, int out_size)
{
    const float* X = (const float*)d_in[0];
    const float* Y = (const float*)d_in[1];
    float* out = (float*)d_out;

    float *Mp, *MTp, *TRp, *TCp, *ap, *bp;
    cudaGetSymbolAddress((void**)&Mp,  g_M);
    cudaGetSymbolAddress((void**)&MTp, g_MT);
    cudaGetSymbolAddress((void**)&TRp, g_TR);
    cudaGetSymbolAddress((void**)&TCp, g_TC);
    cudaGetSymbolAddress((void**)&ap,  g_a);
    cudaGetSymbolAddress((void**)&bp,  g_b);

    init_b_kernel<<<BDIM / 8, 256>>>(Y);

    dim3 ggrid(BDIM / 128, BDIM / 128);
    gemm_kernel<<<ggrid, 256>>>(X, Y);

    tilemax_kernel<<<2048, 256>>>();

    for (int it = 0; it < NITER; it++) {
        lse_sparse_kernel<<<BDIM / 8, 256>>>(Mp,  TRp, bp, ap);  // a = -lse_row(M + b)
        lse_sparse_kernel<<<BDIM / 8, 256>>>(MTp, TCp, ap, bp);  // b = -lse_col(M + a)
    }

    argmax_gather_kernel<<<BDIM / 8, 256>>>(Y, out);
}

// round 6
// speedup vs baseline: 1.3355x; 1.3355x over previous
#include <cuda_runtime.h>
#include <cstdint>
#include <cstddef>

#define BDIM 8192
#define CDIM 256
#define NITER 100
#define MAXROWS 64
#define L2E 1.4426950408889634f
#define LN2 0.69314718055994531f

// Scratch: __device__ globals (no cudaMalloc allowed)
__device__ __align__(256) float g_M [(size_t)BDIM * BDIM];  // M[i][j]  = 2*x_i.y_j
__device__ __align__(256) float g_MT[(size_t)BDIM * BDIM];  // MT[j][i] = M[i][j]
__device__ __align__(256) float g_a[BDIM];
__device__ __align__(256) float g_b[BDIM];

__device__ __forceinline__ float ex2f(float x) {
    float y; asm("ex2.approx.f32 %0, %1;" : "=f"(y) : "f"(x)); return y;
}
__device__ __forceinline__ float lg2f(float x) {
    float y; asm("lg2.approx.f32 %0, %1;" : "=f"(y) : "f"(x)); return y;
}

// ---------------------------------------------------------------------------
// b init: b[j] = -||y_j||^2   (one warp per row, 8 rows per block)
// ---------------------------------------------------------------------------
__global__ __launch_bounds__(256) void init_b_kernel(const float* __restrict__ Y)
{
    int warp = threadIdx.x >> 5, lane = threadIdx.x & 31;
    int row = (blockIdx.x << 3) + warp;
    const float4* yr = (const float4*)Y + (size_t)row * (CDIM / 4);
    float4 v0 = yr[lane];
    float4 v1 = yr[lane + 32];
    float ss = 0.f;
    ss = fmaf(v0.x, v0.x, ss); ss = fmaf(v0.y, v0.y, ss);
    ss = fmaf(v0.z, v0.z, ss); ss = fmaf(v0.w, v0.w, ss);
    ss = fmaf(v1.x, v1.x, ss); ss = fmaf(v1.y, v1.y, ss);
    ss = fmaf(v1.z, v1.z, ss); ss = fmaf(v1.w, v1.w, ss);
    #pragma unroll
    for (int off = 16; off; off >>= 1)
        ss += __shfl_xor_sync(0xffffffffu, ss, off);
    if (lane == 0) g_b[row] = -ss;
}

// ---------------------------------------------------------------------------
// GEMM: M = 2 * X * Y^T, plus transposed copy MT.
// ---------------------------------------------------------------------------
__global__ __launch_bounds__(256) void gemm_kernel(const float* __restrict__ X,
                                                   const float* __restrict__ Y)
{
    __shared__ float As[16][128];
    __shared__ float Bs[16][128];

    const int tid = threadIdx.x;
    const int tx = tid & 15;
    const int ty = tid >> 4;
    const int i0 = blockIdx.y << 7;
    const int j0 = blockIdx.x << 7;

    const float4* X4 = (const float4*)X;
    const float4* Y4 = (const float4*)Y;

    float acc[8][8];
    #pragma unroll
    for (int r = 0; r < 8; r++)
        #pragma unroll
        for (int c = 0; c < 8; c++) acc[r][c] = 0.f;

    for (int k0 = 0; k0 < CDIM; k0 += 16) {
        #pragma unroll
        for (int p = 0; p < 2; p++) {
            int f = tid + (p << 8);
            int r = f >> 2;
            int q = f & 3;
            float4 a = X4[(size_t)(i0 + r) * (CDIM / 4) + (k0 >> 2) + q];
            As[q * 4 + 0][r] = a.x; As[q * 4 + 1][r] = a.y;
            As[q * 4 + 2][r] = a.z; As[q * 4 + 3][r] = a.w;
            float4 b = Y4[(size_t)(j0 + r) * (CDIM / 4) + (k0 >> 2) + q];
            Bs[q * 4 + 0][r] = b.x; Bs[q * 4 + 1][r] = b.y;
            Bs[q * 4 + 2][r] = b.z; Bs[q * 4 + 3][r] = b.w;
        }
        __syncthreads();
        #pragma unroll
        for (int kk = 0; kk < 16; kk++) {
            float af[8], bf[8];
            *(float4*)&af[0] = *(const float4*)&As[kk][ty * 8];
            *(float4*)&af[4] = *(const float4*)&As[kk][ty * 8 + 4];
            *(float4*)&bf[0] = *(const float4*)&Bs[kk][tx * 8];
            *(float4*)&bf[4] = *(const float4*)&Bs[kk][tx * 8 + 4];
            #pragma unroll
            for (int r = 0; r < 8; r++)
                #pragma unroll
                for (int c = 0; c < 8; c++)
                    acc[r][c] = fmaf(af[r], bf[c], acc[r][c]);
        }
        __syncthreads();
    }

    #pragma unroll
    for (int r = 0; r < 8; r++) {
        int i = i0 + ty * 8 + r;
        float4 w0 = make_float4(2.f * acc[r][0], 2.f * acc[r][1],
                                2.f * acc[r][2], 2.f * acc[r][3]);
        float4 w1 = make_float4(2.f * acc[r][4], 2.f * acc[r][5],
                                2.f * acc[r][6], 2.f * acc[r][7]);
        float4* dst = (float4*)(g_M + (size_t)i * BDIM + j0 + tx * 8);
        dst[0] = w0; dst[1] = w1;
    }
    #pragma unroll
    for (int c = 0; c < 8; c++) {
        int j = j0 + tx * 8 + c;
        float4 t0 = make_float4(2.f * acc[0][c], 2.f * acc[1][c],
                                2.f * acc[2][c], 2.f * acc[3][c]);
        float4 t1 = make_float4(2.f * acc[4][c], 2.f * acc[5][c],
                                2.f * acc[6][c], 2.f * acc[7][c]);
        float4* dst = (float4*)(g_MT + (size_t)j * BDIM + i0 + ty * 8);
        dst[0] = t0; dst[1] = t1;
    }
}

// ---------------------------------------------------------------------------
// Dense LSE pass, single-wave balanced:
//   dst[row] = -logsumexp_j( Mmat[row][j] + src[j] )
// Grid = 2*num_SMs blocks of 512 threads (2 resident/SM, exactly one wave).
// Block bi owns rows [8192*bi/nblk, 8192*(bi+1)/nblk). Work unit = 1024-col
// chunk; chunks striped statically over the 16 warps (deterministic).
// Each chunk -> exact local (max, sum) pair in registers; one barrier; tiny
// per-row 8-way combine.
// ---------------------------------------------------------------------------
__global__ __launch_bounds__(512, 2) void lse_pass_kernel(const float* __restrict__ Mmat,
                                                          const float* __restrict__ src,
                                                          float* __restrict__ dst)
{
    __shared__ float sb[BDIM];
    __shared__ float pm[MAXROWS * 8];
    __shared__ float ps[MAXROWS * 8];

    const int tid  = threadIdx.x;
    const int lane = tid & 31, warp = tid >> 5;
    const int nw   = blockDim.x >> 5;                 // 16 warps
    const int nblk = gridDim.x;
    const int r0   = (int)(((long long)BDIM * blockIdx.x) / nblk);
    const int r1   = (int)(((long long)BDIM * (blockIdx.x + 1)) / nblk);
    const int nrows = r1 - r0;
    const int nch   = nrows << 3;                     // 8 chunks per row

    // stage src
    float4* sb4 = (float4*)sb;
    const float4* s4 = (const float4*)src;
    #pragma unroll
    for (int k = 0; k < 4; k++) sb4[tid + 512 * k] = s4[tid + 512 * k];
    __syncthreads();

    for (int c = warp; c < nch; c += nw) {
        const int r = c >> 3;
        const int cb = (c & 7) << 8;                  // chunk base, float4 units
        const float4* m4 = (const float4*)(Mmat + ((size_t)(r0 + r) << 13)) + cb + lane;
        const float4* b4 = sb4 + cb + lane;

        float4 v[8];
        #pragma unroll
        for (int u = 0; u < 8; u++) {
            float4 mm = __ldcs(m4 + 32 * u);
            float4 bb = b4[32 * u];
            v[u].x = mm.x + bb.x; v[u].y = mm.y + bb.y;
            v[u].z = mm.z + bb.z; v[u].w = mm.w + bb.w;
        }
        float t[8];
        #pragma unroll
        for (int u = 0; u < 8; u++)
            t[u] = fmaxf(fmaxf(v[u].x, v[u].y), fmaxf(v[u].z, v[u].w));
        float lmax = fmaxf(fmaxf(fmaxf(t[0], t[1]), fmaxf(t[2], t[3])),
                           fmaxf(fmaxf(t[4], t[5]), fmaxf(t[6], t[7])));
        #pragma unroll
        for (int off = 16; off; off >>= 1)
            lmax = fmaxf(lmax, __shfl_xor_sync(0xffffffffu, lmax, off));

        const float mk = lmax * L2E;
        float s = 0.f;
        #pragma unroll
        for (int u = 0; u < 8; u++) {
            s += ex2f(fmaf(v[u].x, L2E, -mk));
            s += ex2f(fmaf(v[u].y, L2E, -mk));
            s += ex2f(fmaf(v[u].z, L2E, -mk));
            s += ex2f(fmaf(v[u].w, L2E, -mk));
        }
        #pragma unroll
        for (int off = 16; off; off >>= 1)
            s += __shfl_xor_sync(0xffffffffu, s, off);

        if (lane == 0) { pm[c] = lmax; ps[c] = s; }
    }
    __syncthreads();

    // per-row combine of 8 (m,s) pairs (deterministic fixed order)
    for (int r = tid; r < nrows; r += blockDim.x) {
        float m = pm[r * 8];
        #pragma unroll
        for (int k = 1; k < 8; k++) m = fmaxf(m, pm[r * 8 + k]);
        float s = 0.f;
        #pragma unroll
        for (int k = 0; k < 8; k++)
            s += ps[r * 8 + k] * ex2f((pm[r * 8 + k] - m) * L2E);
        dst[r0 + r] = -(m + lg2f(s) * LN2);
    }
}

// ---------------------------------------------------------------------------
// Final: out[i][:] = y[ argmax_j (M[i][j] + b[j]) ][:]   (full scan, runs once)
// ---------------------------------------------------------------------------
__global__ __launch_bounds__(256) void argmax_gather_kernel(const float* __restrict__ Y,
                                                            float* __restrict__ out)
{
    __shared__ float sb[BDIM];
    __shared__ float sval[8];
    __shared__ int   sidx[8];
    __shared__ int   sjbest;
    const int tid = threadIdx.x;
    const int lane = tid & 31, warp = tid >> 5;

    float4* sb4 = (float4*)sb;
    const float4* s4 = (const float4*)g_b;
    #pragma unroll
    for (int k = 0; k < 8; k++) sb4[tid + 256 * k] = s4[tid + 256 * k];
    __syncthreads();

    const int row0 = blockIdx.x << 3;
    for (int rr = 0; rr < 8; rr++) {
        const int row = row0 + rr;
        const float4* m4 = (const float4*)(g_M + (size_t)row * BDIM);

        float best = -3.0e38f;
        int bidx = 0x7fffffff;
        #pragma unroll
        for (int k = 0; k < 8; k++) {
            int f = tid + 256 * k;
            float4 m = __ldcs(m4 + f);
            float4 bb = sb4[f];
            float vx = m.x + bb.x, vy = m.y + bb.y, vz = m.z + bb.z, vw = m.w + bb.w;
            int j = f * 4;
            if (vx > best || (vx == best && j     < bidx)) { best = vx; bidx = j; }
            if (vy > best || (vy == best && j + 1 < bidx)) { best = vy; bidx = j + 1; }
            if (vz > best || (vz == best && j + 2 < bidx)) { best = vz; bidx = j + 2; }
            if (vw > best || (vw == best && j + 3 < bidx)) { best = vw; bidx = j + 3; }
        }
        #pragma unroll
        for (int off = 16; off; off >>= 1) {
            float ov = __shfl_xor_sync(0xffffffffu, best, off);
            int   oi = __shfl_xor_sync(0xffffffffu, bidx, off);
            if (ov > best || (ov == best && oi < bidx)) { best = ov; bidx = oi; }
        }
        if (lane == 0) { sval[warp] = best; sidx[warp] = bidx; }
        __syncthreads();
        if (tid == 0) {
            float bv = sval[0]; int bj = sidx[0];
            #pragma unroll
            for (int w = 1; w < 8; w++) {
                if (sval[w] > bv || (sval[w] == bv && sidx[w] < bj)) {
                    bv = sval[w]; bj = sidx[w];
                }
            }
            sjbest = bj;
        }
        __syncthreads();
        out[(size_t)row * CDIM + tid] = Y[(size_t)sjbest * CDIM + tid];
        __syncthreads();
    }
}

// ---------------------------------------------------------------------------
extern "C" void kernel_launch(void* const* d_in, const int* in_sizes, int n_in,
                              void* d_out, int out_size)
{
    const float* X = (const float*)d_in[0];
    const float* Y = (const float*)d_in[1];
    float* out = (float*)d_out;

    float *Mp, *MTp, *ap, *bp;
    cudaGetSymbolAddress((void**)&Mp,  g_M);
    cudaGetSymbolAddress((void**)&MTp, g_MT);
    cudaGetSymbolAddress((void**)&ap,  g_a);
    cudaGetSymbolAddress((void**)&bp,  g_b);

    int nsm = 148;
    cudaDeviceGetAttribute(&nsm, cudaDevAttrMultiProcessorCount, 0);
    int grid = 2 * nsm;
    if (grid < BDIM / MAXROWS) grid = BDIM / MAXROWS;   // keep nrows <= MAXROWS

    init_b_kernel<<<BDIM / 8, 256>>>(Y);

    dim3 ggrid(BDIM / 128, BDIM / 128);
    gemm_kernel<<<ggrid, 256>>>(X, Y);

    for (int it = 0; it < NITER; it++) {
        lse_pass_kernel<<<grid, 512>>>(Mp,  bp, ap);   // a = -lse_row(M + b)
        lse_pass_kernel<<<grid, 512>>>(MTp, ap, bp);   // b = -lse_col(M + a)
    }

    argmax_gather_kernel<<<BDIM / 8, 256>>>(Y, out);
}